// round 16
// baseline (speedup 1.0000x reference)
#include <cuda_runtime.h>
#include <cuda_bf16.h>

#define NGRAPH 1024
#define NNODE 360
#define NHEAD 8
#define DFEAT 256

typedef unsigned long long u64;

// softmax(w), each weight duplicated (a,a) as u64; row n = 4 x ulonglong2.
__device__ __align__(16) ulonglong2 g_attn[NNODE * 4];   // 23040 B

__device__ __forceinline__ u64 ffma2(u64 a, u64 b, u64 c) {
    u64 d;
    asm("fma.rn.f32x2 %0, %1, %2, %3;" : "=l"(d) : "l"(a), "l"(b), "l"(c));
    return d;
}
// streaming (evict-first) 8B global load
__device__ __forceinline__ u64 ldcs_u64(const u64* p) {
    u64 r;
    asm("ld.global.cs.u64 %0, [%1];" : "=l"(r) : "l"(p));
    return r;
}

// ---------------------------------------------------------------------------
// Kernel 1: softmax over nodes, one block per head (8 blocks, 128 thr).
// __expf fast path; deterministic fixed-order reduction. Writes duplicated
// (a,a) u64 per (n, h) to g_attn.
// ---------------------------------------------------------------------------
__global__ void __launch_bounds__(128) softmax_k(const float* __restrict__ w) {
    __shared__ float s_e[NNODE];
    __shared__ float s_part[128];
    const int h = blockIdx.x;
    const int t = threadIdx.x;

    float p = 0.f;
    for (int n = t; n < NNODE; n += 128) {    // fixed order per thread
        float e = __expf(w[n * NHEAD + h]);
        s_e[n] = e;
        p += e;
    }
    s_part[t] = p;
    __syncthreads();
    if (t < 64) s_part[t] += s_part[t + 64];
    __syncthreads();
    if (t < 32) {
        float q = s_part[t] + s_part[t + 32];
        #pragma unroll
        for (int off = 16; off > 0; off >>= 1)
            q += __shfl_down_sync(0xFFFFFFFFu, q, off);
        if (t == 0) s_part[0] = q;
    }
    __syncthreads();
    const float inv = 1.f / s_part[0];

    u64* ga = (u64*)g_attn;                   // [NNODE][NHEAD] u64 slots
    for (int n = t; n < NNODE; n += 128) {
        unsigned int ai = __float_as_uint(s_e[n] * inv);
        ga[n * NHEAD + h] = (u64)ai | ((u64)ai << 32);
    }
}

// ---------------------------------------------------------------------------
// Kernel 2: streaming pool. Grid 1024 (CTA = graph), 128 THREADS; thread t
// owns float2 column t (floats 2t, 2t+1). Low register footprint (8 u64
// accs + 4-row chunk bufs) -> 7 CTAs/SM = 28 warps/SM (2x R12) for latency
// hiding. 90 chunks of 4 rows, 3-deep software pipeline, ld.global.cs.
// Per-output-element accumulation order identical to R12 (bit-identical).
// ---------------------------------------------------------------------------
#define CROWS 4
#define NCHUNK 90

struct Chunk { u64 v[CROWS]; };

__device__ __forceinline__ void load_chunk(Chunk& ck, const u64* xp, int c) {
    #pragma unroll
    for (int j = 0; j < CROWS; ++j)
        ck.v[j] = ldcs_u64(xp + (size_t)(c * CROWS + j) * (DFEAT / 2));
}

__device__ __forceinline__ void compute_chunk(const Chunk& ck,
                                              const ulonglong2* s_attn, int c,
                                              u64* acc) {
    const int n0 = c * CROWS;
    #pragma unroll
    for (int j = 0; j < CROWS; ++j) {
        const ulonglong2 p0 = s_attn[(n0 + j) * 4 + 0];
        const ulonglong2 p1 = s_attn[(n0 + j) * 4 + 1];
        const ulonglong2 p2 = s_attn[(n0 + j) * 4 + 2];
        const ulonglong2 p3 = s_attn[(n0 + j) * 4 + 3];
        const u64 v = ck.v[j];
        acc[0] = ffma2(v, p0.x, acc[0]);
        acc[1] = ffma2(v, p0.y, acc[1]);
        acc[2] = ffma2(v, p1.x, acc[2]);
        acc[3] = ffma2(v, p1.y, acc[3]);
        acc[4] = ffma2(v, p2.x, acc[4]);
        acc[5] = ffma2(v, p2.y, acc[5]);
        acc[6] = ffma2(v, p3.x, acc[6]);
        acc[7] = ffma2(v, p3.y, acc[7]);
    }
}

__global__ void __launch_bounds__(128, 7) pool_k(const float* __restrict__ x,
                                                 float* __restrict__ out) {
    __shared__ __align__(16) ulonglong2 s_attn[NNODE * 4];   // 23040 B

    const int t = threadIdx.x;
    const int b = blockIdx.x;

    // x row = 128 u64 (float2) entries; thread reads entry t of each row.
    const u64* xp = (const u64*)x + (size_t)b * NNODE * (DFEAT / 2) + t;

    // prologue: chunks 0,1 in flight before the smem fill
    Chunk b0, b1, b2;
    load_chunk(b0, xp, 0);
    load_chunk(b1, xp, 1);

    #pragma unroll
    for (int i = t; i < NNODE * 4; i += 128)
        s_attn[i] = g_attn[i];
    __syncthreads();

    u64 acc[NHEAD];
    #pragma unroll
    for (int h = 0; h < NHEAD; ++h) acc[h] = 0ull;

    // steady state: while computing chunk c, chunks c+1, c+2 in flight
    #pragma unroll 1
    for (int c = 0; c < NCHUNK - 6; c += 3) {
        load_chunk(b2, xp, c + 2);  compute_chunk(b0, s_attn, c,     acc);
        load_chunk(b0, xp, c + 3);  compute_chunk(b1, s_attn, c + 1, acc);
        load_chunk(b1, xp, c + 4);  compute_chunk(b2, s_attn, c + 2, acc);
    }
    // epilogue: chunks 84..89 (84,85 already in flight in b0,b1)
    load_chunk(b2, xp, 86);  compute_chunk(b0, s_attn, 84, acc);
    load_chunk(b0, xp, 87);  compute_chunk(b1, s_attn, 85, acc);
    load_chunk(b1, xp, 88);  compute_chunk(b2, s_attn, 86, acc);
    load_chunk(b2, xp, 89);  compute_chunk(b0, s_attn, 87, acc);
    compute_chunk(b1, s_attn, 88, acc);
    compute_chunk(b2, s_attn, 89, acc);

    // out[b, h*256 + 2t .. 2t+1] -> u64 lane b*1024 + h*128 + t
    u64* o = (u64*)out + (size_t)b * (NHEAD * DFEAT / 2) + t;
    #pragma unroll
    for (int h = 0; h < NHEAD; ++h)
        o[h * (DFEAT / 2)] = acc[h];
}

extern "C" void kernel_launch(void* const* d_in, const int* in_sizes, int n_in,
                              void* d_out, int out_size) {
    const float* x = (const float*)d_in[0];   // [B*N, D] fp32
    // d_in[1] = batch (int64): exactly repeat(arange(B), N); layout only, unused
    const float* w = (const float*)d_in[2];   // [N, H] fp32
    float* out = (float*)d_out;               // [B, H*D] fp32

    softmax_k<<<8, 128>>>(w);
    pool_k<<<NGRAPH, 128>>>(x, out);
}

// round 17
// speedup vs baseline: 1.1924x; 1.1924x over previous
#include <cuda_runtime.h>
#include <cuda_bf16.h>

#define NGRAPH 1024
#define NNODE 360
#define NHEAD 8
#define DFEAT 256

typedef unsigned long long u64;

// softmax(w), each weight duplicated (a,a) as u64; row n = 4 x ulonglong2.
__device__ __align__(16) ulonglong2 g_attn[NNODE * 4];   // 23040 B

__device__ __forceinline__ u64 ffma2(u64 a, u64 b, u64 c) {
    u64 d;
    asm("fma.rn.f32x2 %0, %1, %2, %3;" : "=l"(d) : "l"(a), "l"(b), "l"(c));
    return d;
}

// ---------------------------------------------------------------------------
// Kernel 1: softmax over nodes, one block per head (8 blocks, 128 thr).
// __expf fast path (~0.6us). Deterministic fixed-order reduction. Writes
// duplicated (a,a) u64 per (n, h) to g_attn.
// ---------------------------------------------------------------------------
__global__ void __launch_bounds__(128) softmax_k(const float* __restrict__ w) {
    __shared__ float s_e[NNODE];
    __shared__ float s_part[128];
    const int h = blockIdx.x;
    const int t = threadIdx.x;

    float p = 0.f;
    for (int n = t; n < NNODE; n += 128) {    // fixed order per thread
        float e = __expf(w[n * NHEAD + h]);
        s_e[n] = e;
        p += e;
    }
    s_part[t] = p;
    __syncthreads();
    if (t < 64) s_part[t] += s_part[t + 64];
    __syncthreads();
    if (t < 32) {
        float q = s_part[t] + s_part[t + 32];
        #pragma unroll
        for (int off = 16; off > 0; off >>= 1)
            q += __shfl_down_sync(0xFFFFFFFFu, q, off);
        if (t == 0) s_part[0] = q;
    }
    __syncthreads();
    const float inv = 1.f / s_part[0];

    u64* ga = (u64*)g_attn;                   // [NNODE][NHEAD] u64 slots
    for (int n = t; n < NNODE; n += 128) {
        unsigned int ai = __float_as_uint(s_e[n] * inv);
        ga[n * NHEAD + h] = (u64)ai | ((u64)ai << 32);
    }
}

// ---------------------------------------------------------------------------
// Kernel 2: R5 streaming pool VERBATIM (best measured: 62.8us, 76.6% DRAM).
// Grid 1024 (CTA = graph), 64 threads; thread t owns float4 column t.
// 45 chunks of 8 rows, 2-deep symmetric software pipeline: next chunk's
// 8x LDG.128 issue before current chunk's FFMA phase (~4KB/warp in flight,
// ~56KB/SM at 7 CTAs/SM).
// ---------------------------------------------------------------------------
struct Chunk { ulonglong2 v[8]; };

__device__ __forceinline__ void load_chunk(Chunk& ck, const ulonglong2* xp, int c) {
    #pragma unroll
    for (int j = 0; j < 8; ++j)
        ck.v[j] = xp[(size_t)(c * 8 + j) * (DFEAT / 4)];
}

__device__ __forceinline__ void compute_chunk(const Chunk& ck,
                                              const ulonglong2* s_attn, int c,
                                              u64* accA, u64* accB) {
    const int n0 = c * 8;
    #pragma unroll
    for (int j = 0; j < 8; ++j) {
        const ulonglong2 p0 = s_attn[(n0 + j) * 4 + 0];
        const ulonglong2 p1 = s_attn[(n0 + j) * 4 + 1];
        const ulonglong2 p2 = s_attn[(n0 + j) * 4 + 2];
        const ulonglong2 p3 = s_attn[(n0 + j) * 4 + 3];
        const u64 vx = ck.v[j].x, vy = ck.v[j].y;
        accA[0] = ffma2(vx, p0.x, accA[0]);  accB[0] = ffma2(vy, p0.x, accB[0]);
        accA[1] = ffma2(vx, p0.y, accA[1]);  accB[1] = ffma2(vy, p0.y, accB[1]);
        accA[2] = ffma2(vx, p1.x, accA[2]);  accB[2] = ffma2(vy, p1.x, accB[2]);
        accA[3] = ffma2(vx, p1.y, accA[3]);  accB[3] = ffma2(vy, p1.y, accB[3]);
        accA[4] = ffma2(vx, p2.x, accA[4]);  accB[4] = ffma2(vy, p2.x, accB[4]);
        accA[5] = ffma2(vx, p2.y, accA[5]);  accB[5] = ffma2(vy, p2.y, accB[5]);
        accA[6] = ffma2(vx, p3.x, accA[6]);  accB[6] = ffma2(vy, p3.x, accB[6]);
        accA[7] = ffma2(vx, p3.y, accA[7]);  accB[7] = ffma2(vy, p3.y, accB[7]);
    }
}

__global__ void __launch_bounds__(64, 7) pool_k(const float* __restrict__ x,
                                                float* __restrict__ out) {
    __shared__ __align__(16) ulonglong2 s_attn[NNODE * 4];   // 23040 B

    const int t = threadIdx.x;
    const int b = blockIdx.x;

    #pragma unroll
    for (int i = t; i < NNODE * 4; i += 64)
        s_attn[i] = g_attn[i];
    __syncthreads();

    const ulonglong2* xp =
        (const ulonglong2*)x + (size_t)b * NNODE * (DFEAT / 4) + t;

    u64 accA[NHEAD], accB[NHEAD];
    #pragma unroll
    for (int h = 0; h < NHEAD; ++h) { accA[h] = 0ull; accB[h] = 0ull; }

    Chunk bufA, bufB;
    load_chunk(bufA, xp, 0);
    load_chunk(bufB, xp, 1);

    #pragma unroll 1
    for (int c = 0; c < 42; c += 2) {
        compute_chunk(bufA, s_attn, c, accA, accB);
        load_chunk(bufA, xp, c + 2);
        compute_chunk(bufB, s_attn, c + 1, accA, accB);
        load_chunk(bufB, xp, c + 3);
    }
    compute_chunk(bufA, s_attn, 42, accA, accB);
    load_chunk(bufA, xp, 44);
    compute_chunk(bufB, s_attn, 43, accA, accB);
    compute_chunk(bufA, s_attn, 44, accA, accB);

    ulonglong2* o = (ulonglong2*)out + (size_t)b * (NHEAD * DFEAT / 4) + t;
    #pragma unroll
    for (int h = 0; h < NHEAD; ++h)
        o[h * (DFEAT / 4)] = make_ulonglong2(accA[h], accB[h]);
}

extern "C" void kernel_launch(void* const* d_in, const int* in_sizes, int n_in,
                              void* d_out, int out_size) {
    const float* x = (const float*)d_in[0];   // [B*N, D] fp32
    // d_in[1] = batch (int64): exactly repeat(arange(B), N); layout only, unused
    const float* w = (const float*)d_in[2];   // [N, H] fp32
    float* out = (float*)d_out;               // [B, H*D] fp32

    softmax_k<<<8, 128>>>(w);
    pool_k<<<NGRAPH, 64>>>(x, out);
}